// round 15
// baseline (speedup 1.0000x reference)
#include <cuda_runtime.h>
#include <cuda_bf16.h>
#include <cuda_fp16.h>
#include <math.h>
#include <stdint.h>

#define N_A 50000
#define N_B 50000
#define NT  100000
#define NE  800000
#define EHN 1600000
#define CC  128

// ---------------- device scratch (static, no allocation) ----------------
__device__ float  g_agg [NT * 8];
__device__ __half g_x16 [NT * CC];
__device__ __half g_hid16[2 * NT * 64];
__device__ __half g_lin16[NT * CC];
__device__ __half g_m16 [NT * CC];
__device__ __half g_cur16[NT * CC];
__device__ int    g_cnt [NT];
__device__ int    g_offA[N_A + 1];
__device__ int    g_offB[N_B + 1];
__device__ int    g_csrAB[NE];
__device__ int    g_csrBA[NE];
__device__ float  g_Wc  [2 * 64 * 128];
__device__ float  g_bc  [2 * 128];
__device__ __half g_WTpe  [2 * 128 * 192];
__device__ __half g_WTsage[4 * 128 * 256];

// ---------------- helpers ----------------
__device__ __forceinline__ uint32_t smem_u32(const void* p) {
    uint32_t a;
    asm("{ .reg .u64 t; cvta.to.shared.u64 t, %1; cvt.u32.u64 %0, t; }" : "=r"(a) : "l"(p));
    return a;
}

__device__ __forceinline__ uint32_t pack_h2(float2 f) {
    __half2 h = __float22half2_rn(f);
    return *(uint32_t*)&h;
}

__device__ __forceinline__ void mma_f16(float c[4], const uint32_t a[4],
                                        uint32_t b0, uint32_t b1) {
    asm volatile(
        "mma.sync.aligned.m16n8k16.row.col.f32.f16.f16.f32 "
        "{%0,%1,%2,%3}, {%4,%5,%6,%7}, {%8,%9}, {%0,%1,%2,%3};"
        : "+f"(c[0]), "+f"(c[1]), "+f"(c[2]), "+f"(c[3])
        : "r"(a[0]), "r"(a[1]), "r"(a[2]), "r"(a[3]), "r"(b0), "r"(b1));
}

__device__ __forceinline__ void cpasync16(uint32_t daddr, const void* g, bool pred) {
    int sz = pred ? 16 : 0;
    asm volatile("cp.async.cg.shared.global [%0], [%1], 16, %2;"
                 :: "r"(daddr), "l"(g), "r"(sz) : "memory");
}
#define CP_COMMIT() asm volatile("cp.async.commit_group;" ::: "memory")

__device__ __forceinline__ void red4(float* addr, float4 v) {
    asm volatile("red.global.add.v4.f32 [%0], {%1,%2,%3,%4};"
                 :: "l"(addr), "f"(v.x), "f"(v.y), "f"(v.z), "f"(v.w) : "memory");
}

// ---------------- graph preprocessing (merged two-direction kernels) ----------------
__global__ void count2(const int* __restrict__ dstAB, const int* __restrict__ dstBA,
                       int* __restrict__ cntB, int* __restrict__ cntA) {
    int e = blockIdx.x * blockDim.x + threadIdx.x;
    if (e < NE)            atomicAdd(&cntB[dstAB[e]], 1);
    else if (e < 2 * NE)   atomicAdd(&cntA[dstBA[e - NE]], 1);
}

__global__ void scan2(int* __restrict__ cntA, int* __restrict__ offA,
                      int* __restrict__ cntB, int* __restrict__ offB) {
    __shared__ int part[1024];
    int* cnt = blockIdx.x ? cntB : cntA;
    int* off = blockIdx.x ? offB : offA;
    const int N = N_A;
    int tid = threadIdx.x;
    int chunk = (N + 1023) >> 10;
    int start = tid * chunk;
    int end = min(start + chunk, N);
    int s = 0;
    for (int i = start; i < end; i++) s += cnt[i];
    part[tid] = s;
    __syncthreads();
    for (int o = 1; o < 1024; o <<= 1) {
        int t = (tid >= o) ? part[tid - o] : 0;
        __syncthreads();
        part[tid] += t;
        __syncthreads();
    }
    int pre = part[tid] - s;
    for (int i = start; i < end; i++) {
        int c = cnt[i];
        off[i] = pre;
        cnt[i] = pre;
        pre += c;
    }
    if (tid == 1023) off[N] = part[1023];
}

__global__ void fill2(const int* __restrict__ srcAB, const int* __restrict__ dstAB,
                      const int* __restrict__ srcBA, const int* __restrict__ dstBA,
                      int* __restrict__ posB, int* __restrict__ posA,
                      int* __restrict__ csrAB, int* __restrict__ csrBA) {
    int e = blockIdx.x * blockDim.x + threadIdx.x;
    if (e < NE) {
        int p = atomicAdd(&posB[dstAB[e]], 1);
        csrAB[p] = srcAB[e];
    } else if (e < 2 * NE) {
        int i = e - NE;
        int p = atomicAdd(&posA[dstBA[i]], 1);
        csrBA[p] = srcBA[i];
    }
}

__global__ void agg_scatter(const float* __restrict__ PE, const int* __restrict__ hsrc,
                            const int* __restrict__ hdst, float* __restrict__ agg, int E) {
    int e = blockIdx.x * blockDim.x + threadIdx.x;
    if (e >= E) return;
    int s = hsrc[e], d = hdst[e];
    float4 v0 = *(const float4*)(PE + (size_t)s * 8);
    float4 v1 = *(const float4*)(PE + (size_t)s * 8 + 4);
    red4(agg + (size_t)d * 8,     v0);
    red4(agg + (size_t)d * 8 + 4, v1);
}

__global__ void fold_w(const float* __restrict__ W2, const float* __restrict__ peWpe,
                       float* __restrict__ Wc) {
    int idx = blockIdx.x * blockDim.x + threadIdx.x;
    if (idx >= 64 * 128) return;
    int i = idx >> 7, j = idx & 127;
    float s = 0.0f;
    #pragma unroll 8
    for (int p = 0; p < 64; p++) s += W2[i * 64 + p] * peWpe[p * 128 + j];
    Wc[idx] = s;
}

__global__ void fold_b(const float* __restrict__ b2, const float* __restrict__ peWpe,
                       const float* __restrict__ peb, float* __restrict__ bc) {
    int j = threadIdx.x;
    float s = peb[j];
    #pragma unroll 8
    for (int p = 0; p < 64; p++) s += b2[p] * peWpe[p * 128 + j];
    bc[j] = s;
}

__global__ void transpose_pack(const float* __restrict__ Wl, const float* __restrict__ Wr,
                               __half* __restrict__ WT, int Kl, int Kr) {
    int K = Kl + Kr;
    int idx = blockIdx.x * blockDim.x + threadIdx.x;
    if (idx >= 128 * K) return;
    int n = idx / K, k = idx % K;
    float w = (k < Kl) ? Wl[(size_t)k * 128 + n] : Wr[(size_t)(k - Kl) * 128 + n];
    WT[idx] = __float2half_rn(w);
}

__global__ void conv_x16(const float* __restrict__ xA, const float* __restrict__ xB,
                         __half* __restrict__ x16) {
    int idx = blockIdx.x * blockDim.x + threadIdx.x;
    if (idx >= NT * CC / 4) return;
    size_t e = (size_t)idx * 4;
    size_t row = e >> 7;
    const float* src = (row < N_A) ? (xA + e) : (xB + (e - (size_t)N_A * CC));
    float4 v = *(const float4*)src;
    uint2 o;
    o.x = pack_h2(make_float2(v.x, v.y));
    o.y = pack_h2(make_float2(v.z, v.w));
    *(uint2*)(x16 + e) = o;
}

// hid = relu((agg + PE) @ W1 + b1)  — PE self-term folded here (agg holds scatter-sum only)
__global__ void hid_kernel2(const float* __restrict__ agg, const float* __restrict__ PE,
                            const float* __restrict__ W1, const float* __restrict__ b1,
                            __half* __restrict__ hid, int NTn) {
    __shared__ float sW1[2][512];
    __shared__ float sb1[2][64];
    int tid = threadIdx.x;
    for (int i = tid; i < 512; i += 256) { sW1[0][i] = W1[i]; sW1[1][i] = W1[512 + i]; }
    if (tid < 64) { sb1[0][tid] = b1[tid]; sb1[1][tid] = b1[64 + tid]; }
    __syncthreads();
    int r = tid >> 6, j = tid & 63;
    int row = blockIdx.x * 4 + r;
    if (row < NTn) {
        float a[8];
        #pragma unroll
        for (int k = 0; k < 8; k++)
            a[k] = agg[(size_t)row * 8 + k] + PE[(size_t)row * 8 + k];
        #pragma unroll
        for (int l = 0; l < 2; l++) {
            float h = sb1[l][j];
            #pragma unroll
            for (int k = 0; k < 8; k++) h += a[k] * sW1[l][k * 64 + j];
            hid[(size_t)l * NT * 64 + (size_t)row * 64 + j] = __float2half_rn(fmaxf(h, 0.0f));
        }
    }
}

// ---------------- merged CSR mean gather (half in, half out): one warp per dst row ------
__global__ void mean_gather2(const __half* __restrict__ lin16,
                             const int* __restrict__ csrBA, const int* __restrict__ offA,
                             const int* __restrict__ csrAB, const int* __restrict__ offB,
                             __half* __restrict__ m16)
{
    int w = (blockIdx.x * blockDim.x + threadIdx.x) >> 5;
    if (w >= NT) return;
    int lane = threadIdx.x & 31;
    const int* csr; const int* off; int srcBase, r;
    if (w < N_A) { csr = csrBA; off = offA; srcBase = N_A; r = w; }
    else         { csr = csrAB; off = offB; srcBase = 0;   r = w - N_A; }
    int s0 = off[r], s1 = off[r + 1];
    float4 acc = make_float4(0.f, 0.f, 0.f, 0.f);
    int i = s0;
    for (; i + 4 <= s1; i += 4) {
        int i0 = __ldg(csr + i),     i1 = __ldg(csr + i + 1);
        int i2 = __ldg(csr + i + 2), i3 = __ldg(csr + i + 3);
        #pragma unroll
        for (int u = 0; u < 4; u++) {
            int sidx = (u == 0) ? i0 : (u == 1) ? i1 : (u == 2) ? i2 : i3;
            uint2 pk = *(const uint2*)(lin16 + (size_t)(srcBase + sidx) * CC + lane * 4);
            __half2 h0 = *(__half2*)&pk.x;
            __half2 h1 = *(__half2*)&pk.y;
            float2 f0 = __half22float2(h0);
            float2 f1 = __half22float2(h1);
            acc.x += f0.x; acc.y += f0.y; acc.z += f1.x; acc.w += f1.y;
        }
    }
    for (; i < s1; i++) {
        int sidx = __ldg(csr + i);
        uint2 pk = *(const uint2*)(lin16 + (size_t)(srcBase + sidx) * CC + lane * 4);
        __half2 h0 = *(__half2*)&pk.x;
        __half2 h1 = *(__half2*)&pk.y;
        float2 f0 = __half22float2(h0);
        float2 f1 = __half22float2(h1);
        acc.x += f0.x; acc.y += f0.y; acc.z += f1.x; acc.w += f1.y;
    }
    float sc = 1.0f / (float)max(s1 - s0, 1);
    uint2 o;
    o.x = pack_h2(make_float2(acc.x * sc, acc.y * sc));
    o.y = pack_h2(make_float2(acc.z * sc, acc.w * sc));
    *(uint2*)(m16 + (size_t)w * CC + lane * 4) = o;
}

// ---------------- fp16 mma.sync GEMM (2-stage cp.async, merged A/B launch) ----------------
#define T_TILE_H 3072                 // 128 * 24 halfs per tile buffer
#define GEMM_SMEM_F (640 + 4 * (T_TILE_H / 2))

__device__ __forceinline__ void load_tile(
    const __half* __restrict__ X0, int K0, const __half* __restrict__ X1, int K1,
    const __half* __restrict__ WT, int K, int m0, int M, int t,
    uint32_t asAddr, uint32_t bsAddr, int tid)
{
    int kb = t * 16;
    {
        int row = tid >> 1, c = tid & 1;
        int kk = kb + c * 8;
        bool pred = (m0 + row) < M;
        const __half* src = (kk < K0)
            ? X0 + (size_t)(m0 + row) * K0 + kk
            : X1 + (size_t)(m0 + row) * K1 + (kk - K0);
        cpasync16(asAddr + (uint32_t)(row * 24 + c * 8) * 2, src, pred);
    }
    {
        int n = tid >> 1, c = tid & 1;
        cpasync16(bsAddr + (uint32_t)(n * 24 + c * 8) * 2,
                  WT + (size_t)n * K + kb + c * 8, true);
    }
    CP_COMMIT();
}

template<bool DO_LN>
__global__ void __launch_bounds__(256, 2)
gemm_mma(const __half* X0a, const __half* X0b, int K0,
         const __half* X1a, const __half* X1b, int K1,
         const __half* WTa, const __half* WTb, int K,
         const float* biasA, const float* biasB,
         const float* gamA, const float* betA,
         const float* gamB, const float* betB,
         float* outA, float* outB, __half* out16,
         int Ma, int Mb, int blocksA)
{
    extern __shared__ float sm[];
    float* s_bias  = sm;
    float* s_gamma = sm + 128;
    float* s_beta  = sm + 256;
    float* s_sum   = sm + 384;
    float* s_ss    = sm + 512;
    __half* As     = (__half*)(sm + 640);
    __half* Bs     = As + 2 * T_TILE_H;

    bool isB = (int)blockIdx.x >= blocksA;
    const __half* X0  = isB ? X0b  : X0a;
    const __half* X1  = isB ? X1b  : X1a;
    const __half* WT  = isB ? WTb  : WTa;
    const float* bias = isB ? biasB : biasA;
    const float* gamma = isB ? gamB : gamA;
    const float* beta  = isB ? betB : betA;
    float* out = isB ? outB : outA;
    int M  = isB ? Mb : Ma;
    int mrow0 = (isB ? ((int)blockIdx.x - blocksA) : (int)blockIdx.x) * 128;
    size_t row16base = isB ? (size_t)N_A : 0;

    int tid  = threadIdx.x;
    int lane = tid & 31;
    int warp = tid >> 5;
    int wm = warp & 3;
    int wn = warp >> 2;

    if (tid < 128) {
        s_bias[tid] = bias[tid];
        if (DO_LN) {
            s_gamma[tid] = gamma[tid];
            s_beta[tid]  = beta[tid];
            s_sum[tid] = 0.0f;
            s_ss[tid]  = 0.0f;
        }
    }

    uint32_t asAddr = smem_u32(As);
    uint32_t bsAddr = smem_u32(Bs);

    float c[2][8][4];
    #pragma unroll
    for (int mt = 0; mt < 2; mt++)
        #pragma unroll
        for (int nt = 0; nt < 8; nt++)
            #pragma unroll
            for (int j = 0; j < 4; j++) c[mt][nt][j] = 0.0f;

    const int T = K / 16;
    load_tile(X0, K0, X1, K1, WT, K, mrow0, M, 0, asAddr, bsAddr, tid);
    load_tile(X0, K0, X1, K1, WT, K, mrow0, M, 1,
              asAddr + T_TILE_H * 2, bsAddr + T_TILE_H * 2, tid);

    int kq = 2 * (lane & 3);

    for (int t = 0; t < T; t++) {
        if (t + 1 < T) asm volatile("cp.async.wait_group 1;" ::: "memory");
        else           asm volatile("cp.async.wait_group 0;" ::: "memory");
        __syncthreads();

        const __half* Ab = As + (t & 1) * T_TILE_H;
        const __half* Bb = Bs + (t & 1) * T_TILE_H;

        uint32_t a[2][4];
        #pragma unroll
        for (int mt = 0; mt < 2; mt++) {
            int rb = wm * 32 + mt * 16 + (lane >> 2);
            a[mt][0] = *(const uint32_t*)(Ab + rb * 24 + kq);
            a[mt][1] = *(const uint32_t*)(Ab + (rb + 8) * 24 + kq);
            a[mt][2] = *(const uint32_t*)(Ab + rb * 24 + kq + 8);
            a[mt][3] = *(const uint32_t*)(Ab + (rb + 8) * 24 + kq + 8);
        }
        #pragma unroll
        for (int nt = 0; nt < 8; nt++) {
            int nb = wn * 64 + nt * 8 + (lane >> 2);
            uint32_t b0 = *(const uint32_t*)(Bb + nb * 24 + kq);
            uint32_t b1 = *(const uint32_t*)(Bb + nb * 24 + kq + 8);
            mma_f16(c[0][nt], a[0], b0, b1);
            mma_f16(c[1][nt], a[1], b0, b1);
        }
        __syncthreads();
        if (t + 2 < T)
            load_tile(X0, K0, X1, K1, WT, K, mrow0, M, t + 2,
                      asAddr + (uint32_t)(t & 1) * T_TILE_H * 2,
                      bsAddr + (uint32_t)(t & 1) * T_TILE_H * 2, tid);
    }

    // ---- add bias ----
    #pragma unroll
    for (int nt = 0; nt < 8; nt++) {
        int col = wn * 64 + nt * 8 + 2 * (lane & 3);
        float bx = s_bias[col], by = s_bias[col + 1];
        #pragma unroll
        for (int mt = 0; mt < 2; mt++) {
            c[mt][nt][0] += bx; c[mt][nt][1] += by;
            c[mt][nt][2] += bx; c[mt][nt][3] += by;
        }
    }

    if (!DO_LN) {
        #pragma unroll
        for (int mt = 0; mt < 2; mt++)
            #pragma unroll
            for (int h = 0; h < 2; h++) {
                int rloc = wm * 32 + mt * 16 + (lane >> 2) + h * 8;
                int row = mrow0 + rloc;
                if (row < M) {
                    #pragma unroll
                    for (int nt = 0; nt < 8; nt++) {
                        int col = wn * 64 + nt * 8 + 2 * (lane & 3);
                        uint32_t o16 = pack_h2(make_float2(c[mt][nt][h * 2], c[mt][nt][h * 2 + 1]));
                        *(uint32_t*)(out16 + (row16base + row) * 128 + col) = o16;
                    }
                }
            }
        return;
    }

    // ---- LayerNorm + ReLU ----
    #pragma unroll
    for (int mt = 0; mt < 2; mt++)
        #pragma unroll
        for (int h = 0; h < 2; h++) {
            float s = 0.f, q = 0.f;
            #pragma unroll
            for (int nt = 0; nt < 8; nt++) {
                float v0 = c[mt][nt][h * 2], v1 = c[mt][nt][h * 2 + 1];
                s += v0 + v1;
                q += v0 * v0 + v1 * v1;
            }
            s += __shfl_xor_sync(0xffffffffu, s, 1);
            s += __shfl_xor_sync(0xffffffffu, s, 2);
            q += __shfl_xor_sync(0xffffffffu, q, 1);
            q += __shfl_xor_sync(0xffffffffu, q, 2);
            if ((lane & 3) == 0) {
                int rl = wm * 32 + mt * 16 + (lane >> 2) + h * 8;
                atomicAdd(&s_sum[rl], s);
                atomicAdd(&s_ss[rl], q);
            }
        }
    __syncthreads();
    #pragma unroll
    for (int mt = 0; mt < 2; mt++)
        #pragma unroll
        for (int h = 0; h < 2; h++) {
            int rl = wm * 32 + mt * 16 + (lane >> 2) + h * 8;
            int row = mrow0 + rl;
            float mu   = s_sum[rl] * (1.0f / 128.0f);
            float var  = s_ss[rl] * (1.0f / 128.0f) - mu * mu;
            float rstd = rsqrtf(var + 1e-5f);
            if (row < M) {
                #pragma unroll
                for (int nt = 0; nt < 8; nt++) {
                    int col = wn * 64 + nt * 8 + 2 * (lane & 3);
                    float2 o;
                    o.x = fmaxf((c[mt][nt][h * 2]     - mu) * rstd * s_gamma[col]     + s_beta[col],     0.f);
                    o.y = fmaxf((c[mt][nt][h * 2 + 1] - mu) * rstd * s_gamma[col + 1] + s_beta[col + 1], 0.f);
                    if (out)
                        *(float2*)(out + (size_t)row * 128 + col) = o;
                    if (out16)
                        *(uint32_t*)(out16 + (row16base + row) * 128 + col) = pack_h2(o);
                }
            }
        }
}

// ---------------- launch ----------------
extern "C" void kernel_launch(void* const* d_in, const int* in_sizes, int n_in,
                              void* d_out, int out_size)
{
    const float* xA     = (const float*)d_in[0];
    const float* xB     = (const float*)d_in[1];
    const float* PE     = (const float*)d_in[2];
    const int*   edgeAB = (const int*)  d_in[3];
    const int*   edgeBA = (const int*)  d_in[4];
    const int*   hedge  = (const int*)  d_in[5];
    const float* sWl    = (const float*)d_in[6];
    const float* sbl    = (const float*)d_in[7];
    const float* sWr    = (const float*)d_in[8];
    const float* lng    = (const float*)d_in[9];
    const float* lnb    = (const float*)d_in[10];
    const float* pW1    = (const float*)d_in[11];
    const float* pb1    = (const float*)d_in[12];
    const float* pW2    = (const float*)d_in[13];
    const float* pb2    = (const float*)d_in[14];
    const float* peW    = (const float*)d_in[15];
    const float* peb    = (const float*)d_in[16];
    float* out = (float*)d_out;

    float *agg, *Wc, *bc;
    __half *x16, *hid16, *lin16, *m16, *cur16, *WTpe, *WTsage;
    int *cnt, *offA, *offB, *csrAB, *csrBA;
    cudaGetSymbolAddress((void**)&agg,    g_agg);
    cudaGetSymbolAddress((void**)&x16,    g_x16);
    cudaGetSymbolAddress((void**)&hid16,  g_hid16);
    cudaGetSymbolAddress((void**)&lin16,  g_lin16);
    cudaGetSymbolAddress((void**)&m16,    g_m16);
    cudaGetSymbolAddress((void**)&cur16,  g_cur16);
    cudaGetSymbolAddress((void**)&cnt,    g_cnt);
    cudaGetSymbolAddress((void**)&offA,   g_offA);
    cudaGetSymbolAddress((void**)&offB,   g_offB);
    cudaGetSymbolAddress((void**)&csrAB,  g_csrAB);
    cudaGetSymbolAddress((void**)&csrBA,  g_csrBA);
    cudaGetSymbolAddress((void**)&Wc,     g_Wc);
    cudaGetSymbolAddress((void**)&bc,     g_bc);
    cudaGetSymbolAddress((void**)&WTpe,   g_WTpe);
    cudaGetSymbolAddress((void**)&WTsage, g_WTsage);
    int* cntA = cnt;
    int* cntB = cnt + N_A;

    size_t gsm = GEMM_SMEM_F * sizeof(float);
    cudaFuncSetAttribute(gemm_mma<false>, cudaFuncAttributeMaxDynamicSharedMemorySize, (int)gsm);
    cudaFuncSetAttribute(gemm_mma<true>,  cudaFuncAttributeMaxDynamicSharedMemorySize, (int)gsm);

    cudaStream_t s2;
    cudaStreamCreateWithFlags(&s2, cudaStreamNonBlocking);
    cudaEvent_t e0, e_wt, e_csr;
    cudaEventCreateWithFlags(&e0,    cudaEventDisableTiming);
    cudaEventCreateWithFlags(&e_wt,  cudaEventDisableTiming);
    cudaEventCreateWithFlags(&e_csr, cudaEventDisableTiming);

    cudaEventRecord(e0, 0);
    cudaStreamWaitEvent(s2, e0, 0);

    // ---- s2: x16 conversion + weight folds/transposes, then compact CSR chain ----
    conv_x16<<<(NT * CC / 4 + 255) / 256, 256, 0, s2>>>(xA, xB, x16);
    for (int l = 0; l < 2; l++) {
        const float* peWpe = peW + (size_t)l * 192 * 128 + 128 * 128;
        fold_w<<<32, 256, 0, s2>>>(pW2 + l * 4096, peWpe, Wc + (size_t)l * 64 * 128);
        fold_b<<<1, 128, 0, s2>>>(pb2 + l * 64, peWpe, peb + l * 128, bc + l * 128);
        transpose_pack<<<(128 * 192 + 255) / 256, 256, 0, s2>>>(
            peW + (size_t)l * 192 * 128, Wc + (size_t)l * 64 * 128,
            WTpe + (size_t)l * 128 * 192, 128, 64);
        for (int e = 0; e < 2; e++) {
            int li = l * 2 + e;
            transpose_pack<<<(128 * 256 + 255) / 256, 256, 0, s2>>>(
                sWl + (size_t)li * 16384, sWr + (size_t)li * 16384,
                WTsage + (size_t)li * 128 * 256, 128, 128);
        }
    }
    cudaEventRecord(e_wt, s2);

    cudaMemsetAsync(cnt, 0, NT * sizeof(int), s2);
    count2<<<(2 * NE + 255) / 256, 256, 0, s2>>>(edgeAB + NE, edgeBA + NE, cntB, cntA);
    scan2<<<2, 1024, 0, s2>>>(cntA, offA, cntB, offB);
    fill2<<<(2 * NE + 255) / 256, 256, 0, s2>>>(edgeAB, edgeAB + NE, edgeBA, edgeBA + NE,
                                                cntB, cntA, csrAB, csrBA);
    cudaEventRecord(e_csr, s2);

    // ---- default stream: critical path (agg memset + scatter; PE self-term folded into hid) ----
    cudaMemsetAsync(agg, 0, (size_t)NT * 8 * sizeof(float));
    agg_scatter<<<(EHN + 255) / 256, 256>>>(PE, hedge, hedge + EHN, agg, EHN);
    hid_kernel2<<<(NT + 3) / 4, 256>>>(agg, PE, pW1, pb1, hid16, NT);

    cudaStreamWaitEvent(0, e_wt, 0);

    const __half* srcA = x16;
    const __half* srcB = x16 + (size_t)N_A * CC;
    const int blocksA = (N_A + 127) / 128;
    dim3 gGrid(2 * blocksA);
    bool joined_csr = false;

    for (int l = 0; l < 2; l++) {
        const __half* hl = hid16 + (size_t)l * NT * 64;

        gemm_mma<false><<<gGrid, 256, gsm>>>(
            srcA, srcB, 128,
            hl, hl + (size_t)N_A * 64, 64,
            WTpe + (size_t)l * 128 * 192, WTpe + (size_t)l * 128 * 192, 192,
            bc + l * 128, bc + l * 128,
            nullptr, nullptr, nullptr, nullptr,
            nullptr, nullptr, lin16, N_A, N_B, blocksA);

        if (!joined_csr) { cudaStreamWaitEvent(0, e_csr, 0); joined_csr = true; }

        mean_gather2<<<(NT * 32 + 255) / 256, 256>>>(lin16, csrBA, offA,
                                                     csrAB, offB, m16);

        float* outA = (l == 1) ? out                    : nullptr;
        float* outB = (l == 1) ? out + (size_t)N_A * CC : nullptr;
        __half* o16 = (l == 0) ? cur16 : nullptr;

        gemm_mma<true><<<gGrid, 256, gsm>>>(
            m16, m16 + (size_t)N_A * CC, 128,
            lin16, lin16 + (size_t)N_A * CC, 128,
            WTsage + (size_t)(l * 2 + 1) * 128 * 256,
            WTsage + (size_t)(l * 2 + 0) * 128 * 256, 256,
            sbl + (l * 2 + 1) * 128, sbl + (l * 2 + 0) * 128,
            lng + (l * 2 + 0) * 128, lnb + (l * 2 + 0) * 128,
            lng + (l * 2 + 1) * 128, lnb + (l * 2 + 1) * 128,
            outA, outB, o16, N_A, N_B, blocksA);

        srcA = cur16;
        srcB = cur16 + (size_t)N_A * CC;
    }
}

// round 16
// speedup vs baseline: 1.0373x; 1.0373x over previous
#include <cuda_runtime.h>
#include <cuda_bf16.h>
#include <cuda_fp16.h>
#include <math.h>
#include <stdint.h>

#define N_A 50000
#define N_B 50000
#define NT  100000
#define NE  800000
#define EHN 1600000
#define CC  128

// ---------------- device scratch (static, no allocation) ----------------
__device__ float  g_agg [NT * 8];
__device__ __half g_x16 [NT * CC];
__device__ __half g_hid16[2 * NT * 64];
__device__ __half g_lin16[NT * CC];
__device__ __half g_m16 [NT * CC];
__device__ __half g_cur16[NT * CC];
__device__ int    g_cnt [NT];
__device__ int    g_offA[N_A + 1];
__device__ int    g_offB[N_B + 1];
__device__ int    g_csrAB[NE];
__device__ int    g_csrBA[NE];
__device__ float  g_Wc  [2 * 64 * 128];
__device__ float  g_bc  [2 * 128];
__device__ __half g_WTpe  [2 * 128 * 192];
__device__ __half g_WTsage[4 * 128 * 256];

// ---------------- helpers ----------------
__device__ __forceinline__ uint32_t smem_u32(const void* p) {
    uint32_t a;
    asm("{ .reg .u64 t; cvta.to.shared.u64 t, %1; cvt.u32.u64 %0, t; }" : "=r"(a) : "l"(p));
    return a;
}

__device__ __forceinline__ uint32_t pack_h2(float2 f) {
    __half2 h = __float22half2_rn(f);
    return *(uint32_t*)&h;
}

__device__ __forceinline__ void mma_f16(float c[4], const uint32_t a[4],
                                        uint32_t b0, uint32_t b1) {
    asm volatile(
        "mma.sync.aligned.m16n8k16.row.col.f32.f16.f16.f32 "
        "{%0,%1,%2,%3}, {%4,%5,%6,%7}, {%8,%9}, {%0,%1,%2,%3};"
        : "+f"(c[0]), "+f"(c[1]), "+f"(c[2]), "+f"(c[3])
        : "r"(a[0]), "r"(a[1]), "r"(a[2]), "r"(a[3]), "r"(b0), "r"(b1));
}

__device__ __forceinline__ void cpasync16(uint32_t daddr, const void* g, bool pred) {
    int sz = pred ? 16 : 0;
    asm volatile("cp.async.cg.shared.global [%0], [%1], 16, %2;"
                 :: "r"(daddr), "l"(g), "r"(sz) : "memory");
}
#define CP_COMMIT() asm volatile("cp.async.commit_group;" ::: "memory")

__device__ __forceinline__ void red4(float* addr, float4 v) {
    asm volatile("red.global.add.v4.f32 [%0], {%1,%2,%3,%4};"
                 :: "l"(addr), "f"(v.x), "f"(v.y), "f"(v.z), "f"(v.w) : "memory");
}

// ---------------- graph preprocessing (merged two-direction kernels) ----------------
__global__ void count2(const int* __restrict__ dstAB, const int* __restrict__ dstBA,
                       int* __restrict__ cntB, int* __restrict__ cntA) {
    int e = blockIdx.x * blockDim.x + threadIdx.x;
    if (e < NE)            atomicAdd(&cntB[dstAB[e]], 1);
    else if (e < 2 * NE)   atomicAdd(&cntA[dstBA[e - NE]], 1);
}

__global__ void scan2(int* __restrict__ cntA, int* __restrict__ offA,
                      int* __restrict__ cntB, int* __restrict__ offB) {
    __shared__ int part[1024];
    int* cnt = blockIdx.x ? cntB : cntA;
    int* off = blockIdx.x ? offB : offA;
    const int N = N_A;
    int tid = threadIdx.x;
    int chunk = (N + 1023) >> 10;
    int start = tid * chunk;
    int end = min(start + chunk, N);
    int s = 0;
    for (int i = start; i < end; i++) s += cnt[i];
    part[tid] = s;
    __syncthreads();
    for (int o = 1; o < 1024; o <<= 1) {
        int t = (tid >= o) ? part[tid - o] : 0;
        __syncthreads();
        part[tid] += t;
        __syncthreads();
    }
    int pre = part[tid] - s;
    for (int i = start; i < end; i++) {
        int c = cnt[i];
        off[i] = pre;
        cnt[i] = pre;
        pre += c;
    }
    if (tid == 1023) off[N] = part[1023];
}

__global__ void fill2(const int* __restrict__ srcAB, const int* __restrict__ dstAB,
                      const int* __restrict__ srcBA, const int* __restrict__ dstBA,
                      int* __restrict__ posB, int* __restrict__ posA,
                      int* __restrict__ csrAB, int* __restrict__ csrBA) {
    int e = blockIdx.x * blockDim.x + threadIdx.x;
    if (e < NE) {
        int p = atomicAdd(&posB[dstAB[e]], 1);
        csrAB[p] = srcAB[e];
    } else if (e < 2 * NE) {
        int i = e - NE;
        int p = atomicAdd(&posA[dstBA[i]], 1);
        csrBA[p] = srcBA[i];
    }
}

__global__ void agg_scatter(const float* __restrict__ PE, const int* __restrict__ hsrc,
                            const int* __restrict__ hdst, float* __restrict__ agg, int E) {
    int e = blockIdx.x * blockDim.x + threadIdx.x;
    if (e >= E) return;
    int s = hsrc[e], d = hdst[e];
    float4 v0 = *(const float4*)(PE + (size_t)s * 8);
    float4 v1 = *(const float4*)(PE + (size_t)s * 8 + 4);
    red4(agg + (size_t)d * 8,     v0);
    red4(agg + (size_t)d * 8 + 4, v1);
}

__global__ void fold_w(const float* __restrict__ W2, const float* __restrict__ peWpe,
                       float* __restrict__ Wc) {
    int idx = blockIdx.x * blockDim.x + threadIdx.x;
    if (idx >= 64 * 128) return;
    int i = idx >> 7, j = idx & 127;
    float s = 0.0f;
    #pragma unroll 8
    for (int p = 0; p < 64; p++) s += W2[i * 64 + p] * peWpe[p * 128 + j];
    Wc[idx] = s;
}

__global__ void fold_b(const float* __restrict__ b2, const float* __restrict__ peWpe,
                       const float* __restrict__ peb, float* __restrict__ bc) {
    int j = threadIdx.x;
    float s = peb[j];
    #pragma unroll 8
    for (int p = 0; p < 64; p++) s += b2[p] * peWpe[p * 128 + j];
    bc[j] = s;
}

__global__ void transpose_pack(const float* __restrict__ Wl, const float* __restrict__ Wr,
                               __half* __restrict__ WT, int Kl, int Kr) {
    int K = Kl + Kr;
    int idx = blockIdx.x * blockDim.x + threadIdx.x;
    if (idx >= 128 * K) return;
    int n = idx / K, k = idx % K;
    float w = (k < Kl) ? Wl[(size_t)k * 128 + n] : Wr[(size_t)(k - Kl) * 128 + n];
    WT[idx] = __float2half_rn(w);
}

__global__ void conv_x16(const float* __restrict__ xA, const float* __restrict__ xB,
                         __half* __restrict__ x16) {
    int idx = blockIdx.x * blockDim.x + threadIdx.x;
    if (idx >= NT * CC / 4) return;
    size_t e = (size_t)idx * 4;
    size_t row = e >> 7;
    const float* src = (row < N_A) ? (xA + e) : (xB + (e - (size_t)N_A * CC));
    float4 v = *(const float4*)src;
    uint2 o;
    o.x = pack_h2(make_float2(v.x, v.y));
    o.y = pack_h2(make_float2(v.z, v.w));
    *(uint2*)(x16 + e) = o;
}

__global__ void hid_kernel2(const float* __restrict__ agg,
                            const float* __restrict__ W1, const float* __restrict__ b1,
                            __half* __restrict__ hid, int NTn) {
    __shared__ float sW1[2][512];
    __shared__ float sb1[2][64];
    int tid = threadIdx.x;
    for (int i = tid; i < 512; i += 256) { sW1[0][i] = W1[i]; sW1[1][i] = W1[512 + i]; }
    if (tid < 64) { sb1[0][tid] = b1[tid]; sb1[1][tid] = b1[64 + tid]; }
    __syncthreads();
    int r = tid >> 6, j = tid & 63;
    int row = blockIdx.x * 4 + r;
    if (row < NTn) {
        float a[8];
        #pragma unroll
        for (int k = 0; k < 8; k++) a[k] = agg[(size_t)row * 8 + k];
        #pragma unroll
        for (int l = 0; l < 2; l++) {
            float h = sb1[l][j];
            #pragma unroll
            for (int k = 0; k < 8; k++) h += a[k] * sW1[l][k * 64 + j];
            hid[(size_t)l * NT * 64 + (size_t)row * 64 + j] = __float2half_rn(fmaxf(h, 0.0f));
        }
    }
}

// ---------------- merged CSR mean gather: TWO rows per warp, 16B loads/lane ------------
// lanes [0,16) -> row 2w, lanes [16,32) -> row 2w+1; each lane owns 8 columns (uint4).
__global__ void mean_gather4(const __half* __restrict__ lin16,
                             const int* __restrict__ csrBA, const int* __restrict__ offA,
                             const int* __restrict__ csrAB, const int* __restrict__ offB,
                             __half* __restrict__ m16)
{
    int gw = (blockIdx.x * blockDim.x + threadIdx.x) >> 5;
    int lane = threadIdx.x & 31;
    int r = gw * 2 + (lane >> 4);
    if (r >= NT) return;
    const int* csr; const int* off; int srcBase, rr;
    if (r < N_A) { csr = csrBA; off = offA; srcBase = N_A; rr = r; }
    else         { csr = csrAB; off = offB; srcBase = 0;   rr = r - N_A; }
    int s0 = off[rr], s1 = off[rr + 1];
    int colh = (lane & 15) * 8;

    float a0=0.f,a1=0.f,a2=0.f,a3=0.f,a4=0.f,a5=0.f,a6=0.f,a7=0.f;
    int i = s0;
    for (; i + 2 <= s1; i += 2) {
        int i0 = __ldg(csr + i), i1 = __ldg(csr + i + 1);
        uint4 p0 = *(const uint4*)(lin16 + (size_t)(srcBase + i0) * CC + colh);
        uint4 p1 = *(const uint4*)(lin16 + (size_t)(srcBase + i1) * CC + colh);
        {
            float2 f0 = __half22float2(*(__half2*)&p0.x);
            float2 f1 = __half22float2(*(__half2*)&p0.y);
            float2 f2 = __half22float2(*(__half2*)&p0.z);
            float2 f3 = __half22float2(*(__half2*)&p0.w);
            a0 += f0.x; a1 += f0.y; a2 += f1.x; a3 += f1.y;
            a4 += f2.x; a5 += f2.y; a6 += f3.x; a7 += f3.y;
        }
        {
            float2 f0 = __half22float2(*(__half2*)&p1.x);
            float2 f1 = __half22float2(*(__half2*)&p1.y);
            float2 f2 = __half22float2(*(__half2*)&p1.z);
            float2 f3 = __half22float2(*(__half2*)&p1.w);
            a0 += f0.x; a1 += f0.y; a2 += f1.x; a3 += f1.y;
            a4 += f2.x; a5 += f2.y; a6 += f3.x; a7 += f3.y;
        }
    }
    if (i < s1) {
        int i0 = __ldg(csr + i);
        uint4 p0 = *(const uint4*)(lin16 + (size_t)(srcBase + i0) * CC + colh);
        float2 f0 = __half22float2(*(__half2*)&p0.x);
        float2 f1 = __half22float2(*(__half2*)&p0.y);
        float2 f2 = __half22float2(*(__half2*)&p0.z);
        float2 f3 = __half22float2(*(__half2*)&p0.w);
        a0 += f0.x; a1 += f0.y; a2 += f1.x; a3 += f1.y;
        a4 += f2.x; a5 += f2.y; a6 += f3.x; a7 += f3.y;
    }
    float sc = 1.0f / (float)max(s1 - s0, 1);
    uint4 o;
    o.x = pack_h2(make_float2(a0 * sc, a1 * sc));
    o.y = pack_h2(make_float2(a2 * sc, a3 * sc));
    o.z = pack_h2(make_float2(a4 * sc, a5 * sc));
    o.w = pack_h2(make_float2(a6 * sc, a7 * sc));
    *(uint4*)(m16 + (size_t)r * CC + colh) = o;
}

// ---------------- fp16 mma.sync GEMM (2-stage cp.async, merged A/B launch) ----------------
#define T_TILE_H 3072                 // 128 * 24 halfs per tile buffer
#define GEMM_SMEM_F (640 + 4 * (T_TILE_H / 2))

__device__ __forceinline__ void load_tile(
    const __half* __restrict__ X0, int K0, const __half* __restrict__ X1, int K1,
    const __half* __restrict__ WT, int K, int m0, int M, int t,
    uint32_t asAddr, uint32_t bsAddr, int tid)
{
    int kb = t * 16;
    {
        int row = tid >> 1, c = tid & 1;
        int kk = kb + c * 8;
        bool pred = (m0 + row) < M;
        const __half* src = (kk < K0)
            ? X0 + (size_t)(m0 + row) * K0 + kk
            : X1 + (size_t)(m0 + row) * K1 + (kk - K0);
        cpasync16(asAddr + (uint32_t)(row * 24 + c * 8) * 2, src, pred);
    }
    {
        int n = tid >> 1, c = tid & 1;
        cpasync16(bsAddr + (uint32_t)(n * 24 + c * 8) * 2,
                  WT + (size_t)n * K + kb + c * 8, true);
    }
    CP_COMMIT();
}

template<bool DO_LN>
__global__ void __launch_bounds__(256, 2)
gemm_mma(const __half* X0a, const __half* X0b, int K0,
         const __half* X1a, const __half* X1b, int K1,
         const __half* WTa, const __half* WTb, int K,
         const float* biasA, const float* biasB,
         const float* gamA, const float* betA,
         const float* gamB, const float* betB,
         float* outA, float* outB, __half* out16,
         int Ma, int Mb, int blocksA)
{
    extern __shared__ float sm[];
    float* s_bias  = sm;
    float* s_gamma = sm + 128;
    float* s_beta  = sm + 256;
    float* s_sum   = sm + 384;
    float* s_ss    = sm + 512;
    __half* As     = (__half*)(sm + 640);
    __half* Bs     = As + 2 * T_TILE_H;

    bool isB = (int)blockIdx.x >= blocksA;
    const __half* X0  = isB ? X0b  : X0a;
    const __half* X1  = isB ? X1b  : X1a;
    const __half* WT  = isB ? WTb  : WTa;
    const float* bias = isB ? biasB : biasA;
    const float* gamma = isB ? gamB : gamA;
    const float* beta  = isB ? betB : betA;
    float* out = isB ? outB : outA;
    int M  = isB ? Mb : Ma;
    int mrow0 = (isB ? ((int)blockIdx.x - blocksA) : (int)blockIdx.x) * 128;
    size_t row16base = isB ? (size_t)N_A : 0;

    int tid  = threadIdx.x;
    int lane = tid & 31;
    int warp = tid >> 5;
    int wm = warp & 3;
    int wn = warp >> 2;

    if (tid < 128) {
        s_bias[tid] = bias[tid];
        if (DO_LN) {
            s_gamma[tid] = gamma[tid];
            s_beta[tid]  = beta[tid];
            s_sum[tid] = 0.0f;
            s_ss[tid]  = 0.0f;
        }
    }

    uint32_t asAddr = smem_u32(As);
    uint32_t bsAddr = smem_u32(Bs);

    float c[2][8][4];
    #pragma unroll
    for (int mt = 0; mt < 2; mt++)
        #pragma unroll
        for (int nt = 0; nt < 8; nt++)
            #pragma unroll
            for (int j = 0; j < 4; j++) c[mt][nt][j] = 0.0f;

    const int T = K / 16;
    load_tile(X0, K0, X1, K1, WT, K, mrow0, M, 0, asAddr, bsAddr, tid);
    load_tile(X0, K0, X1, K1, WT, K, mrow0, M, 1,
              asAddr + T_TILE_H * 2, bsAddr + T_TILE_H * 2, tid);

    int kq = 2 * (lane & 3);

    for (int t = 0; t < T; t++) {
        if (t + 1 < T) asm volatile("cp.async.wait_group 1;" ::: "memory");
        else           asm volatile("cp.async.wait_group 0;" ::: "memory");
        __syncthreads();

        const __half* Ab = As + (t & 1) * T_TILE_H;
        const __half* Bb = Bs + (t & 1) * T_TILE_H;

        uint32_t a[2][4];
        #pragma unroll
        for (int mt = 0; mt < 2; mt++) {
            int rb = wm * 32 + mt * 16 + (lane >> 2);
            a[mt][0] = *(const uint32_t*)(Ab + rb * 24 + kq);
            a[mt][1] = *(const uint32_t*)(Ab + (rb + 8) * 24 + kq);
            a[mt][2] = *(const uint32_t*)(Ab + rb * 24 + kq + 8);
            a[mt][3] = *(const uint32_t*)(Ab + (rb + 8) * 24 + kq + 8);
        }
        #pragma unroll
        for (int nt = 0; nt < 8; nt++) {
            int nb = wn * 64 + nt * 8 + (lane >> 2);
            uint32_t b0 = *(const uint32_t*)(Bb + nb * 24 + kq);
            uint32_t b1 = *(const uint32_t*)(Bb + nb * 24 + kq + 8);
            mma_f16(c[0][nt], a[0], b0, b1);
            mma_f16(c[1][nt], a[1], b0, b1);
        }
        __syncthreads();
        if (t + 2 < T)
            load_tile(X0, K0, X1, K1, WT, K, mrow0, M, t + 2,
                      asAddr + (uint32_t)(t & 1) * T_TILE_H * 2,
                      bsAddr + (uint32_t)(t & 1) * T_TILE_H * 2, tid);
    }

    // ---- add bias ----
    #pragma unroll
    for (int nt = 0; nt < 8; nt++) {
        int col = wn * 64 + nt * 8 + 2 * (lane & 3);
        float bx = s_bias[col], by = s_bias[col + 1];
        #pragma unroll
        for (int mt = 0; mt < 2; mt++) {
            c[mt][nt][0] += bx; c[mt][nt][1] += by;
            c[mt][nt][2] += bx; c[mt][nt][3] += by;
        }
    }

    if (!DO_LN) {
        #pragma unroll
        for (int mt = 0; mt < 2; mt++)
            #pragma unroll
            for (int h = 0; h < 2; h++) {
                int rloc = wm * 32 + mt * 16 + (lane >> 2) + h * 8;
                int row = mrow0 + rloc;
                if (row < M) {
                    #pragma unroll
                    for (int nt = 0; nt < 8; nt++) {
                        int col = wn * 64 + nt * 8 + 2 * (lane & 3);
                        uint32_t o16 = pack_h2(make_float2(c[mt][nt][h * 2], c[mt][nt][h * 2 + 1]));
                        *(uint32_t*)(out16 + (row16base + row) * 128 + col) = o16;
                    }
                }
            }
        return;
    }

    // ---- LayerNorm + ReLU ----
    #pragma unroll
    for (int mt = 0; mt < 2; mt++)
        #pragma unroll
        for (int h = 0; h < 2; h++) {
            float s = 0.f, q = 0.f;
            #pragma unroll
            for (int nt = 0; nt < 8; nt++) {
                float v0 = c[mt][nt][h * 2], v1 = c[mt][nt][h * 2 + 1];
                s += v0 + v1;
                q += v0 * v0 + v1 * v1;
            }
            s += __shfl_xor_sync(0xffffffffu, s, 1);
            s += __shfl_xor_sync(0xffffffffu, s, 2);
            q += __shfl_xor_sync(0xffffffffu, q, 1);
            q += __shfl_xor_sync(0xffffffffu, q, 2);
            if ((lane & 3) == 0) {
                int rl = wm * 32 + mt * 16 + (lane >> 2) + h * 8;
                atomicAdd(&s_sum[rl], s);
                atomicAdd(&s_ss[rl], q);
            }
        }
    __syncthreads();
    #pragma unroll
    for (int mt = 0; mt < 2; mt++)
        #pragma unroll
        for (int h = 0; h < 2; h++) {
            int rl = wm * 32 + mt * 16 + (lane >> 2) + h * 8;
            int row = mrow0 + rl;
            float mu   = s_sum[rl] * (1.0f / 128.0f);
            float var  = s_ss[rl] * (1.0f / 128.0f) - mu * mu;
            float rstd = rsqrtf(var + 1e-5f);
            if (row < M) {
                #pragma unroll
                for (int nt = 0; nt < 8; nt++) {
                    int col = wn * 64 + nt * 8 + 2 * (lane & 3);
                    float2 o;
                    o.x = fmaxf((c[mt][nt][h * 2]     - mu) * rstd * s_gamma[col]     + s_beta[col],     0.f);
                    o.y = fmaxf((c[mt][nt][h * 2 + 1] - mu) * rstd * s_gamma[col + 1] + s_beta[col + 1], 0.f);
                    if (out)
                        *(float2*)(out + (size_t)row * 128 + col) = o;
                    if (out16)
                        *(uint32_t*)(out16 + (row16base + row) * 128 + col) = pack_h2(o);
                }
            }
        }
}

// ---------------- launch ----------------
extern "C" void kernel_launch(void* const* d_in, const int* in_sizes, int n_in,
                              void* d_out, int out_size)
{
    const float* xA     = (const float*)d_in[0];
    const float* xB     = (const float*)d_in[1];
    const float* PE     = (const float*)d_in[2];
    const int*   edgeAB = (const int*)  d_in[3];
    const int*   edgeBA = (const int*)  d_in[4];
    const int*   hedge  = (const int*)  d_in[5];
    const float* sWl    = (const float*)d_in[6];
    const float* sbl    = (const float*)d_in[7];
    const float* sWr    = (const float*)d_in[8];
    const float* lng    = (const float*)d_in[9];
    const float* lnb    = (const float*)d_in[10];
    const float* pW1    = (const float*)d_in[11];
    const float* pb1    = (const float*)d_in[12];
    const float* pW2    = (const float*)d_in[13];
    const float* pb2    = (const float*)d_in[14];
    const float* peW    = (const float*)d_in[15];
    const float* peb    = (const float*)d_in[16];
    float* out = (float*)d_out;

    float *agg, *Wc, *bc;
    __half *x16, *hid16, *lin16, *m16, *cur16, *WTpe, *WTsage;
    int *cnt, *offA, *offB, *csrAB, *csrBA;
    cudaGetSymbolAddress((void**)&agg,    g_agg);
    cudaGetSymbolAddress((void**)&x16,    g_x16);
    cudaGetSymbolAddress((void**)&hid16,  g_hid16);
    cudaGetSymbolAddress((void**)&lin16,  g_lin16);
    cudaGetSymbolAddress((void**)&m16,    g_m16);
    cudaGetSymbolAddress((void**)&cur16,  g_cur16);
    cudaGetSymbolAddress((void**)&cnt,    g_cnt);
    cudaGetSymbolAddress((void**)&offA,   g_offA);
    cudaGetSymbolAddress((void**)&offB,   g_offB);
    cudaGetSymbolAddress((void**)&csrAB,  g_csrAB);
    cudaGetSymbolAddress((void**)&csrBA,  g_csrBA);
    cudaGetSymbolAddress((void**)&Wc,     g_Wc);
    cudaGetSymbolAddress((void**)&bc,     g_bc);
    cudaGetSymbolAddress((void**)&WTpe,   g_WTpe);
    cudaGetSymbolAddress((void**)&WTsage, g_WTsage);
    int* cntA = cnt;
    int* cntB = cnt + N_A;

    size_t gsm = GEMM_SMEM_F * sizeof(float);
    cudaFuncSetAttribute(gemm_mma<false>, cudaFuncAttributeMaxDynamicSharedMemorySize, (int)gsm);
    cudaFuncSetAttribute(gemm_mma<true>,  cudaFuncAttributeMaxDynamicSharedMemorySize, (int)gsm);

    cudaStream_t s2;
    cudaStreamCreateWithFlags(&s2, cudaStreamNonBlocking);
    cudaEvent_t e0, e_wt, e_csr;
    cudaEventCreateWithFlags(&e0,    cudaEventDisableTiming);
    cudaEventCreateWithFlags(&e_wt,  cudaEventDisableTiming);
    cudaEventCreateWithFlags(&e_csr, cudaEventDisableTiming);

    cudaEventRecord(e0, 0);
    cudaStreamWaitEvent(s2, e0, 0);

    // ---- s2: x16 conversion + weight folds/transposes, then compact CSR chain ----
    conv_x16<<<(NT * CC / 4 + 255) / 256, 256, 0, s2>>>(xA, xB, x16);
    for (int l = 0; l < 2; l++) {
        const float* peWpe = peW + (size_t)l * 192 * 128 + 128 * 128;
        fold_w<<<32, 256, 0, s2>>>(pW2 + l * 4096, peWpe, Wc + (size_t)l * 64 * 128);
        fold_b<<<1, 128, 0, s2>>>(pb2 + l * 64, peWpe, peb + l * 128, bc + l * 128);
        transpose_pack<<<(128 * 192 + 255) / 256, 256, 0, s2>>>(
            peW + (size_t)l * 192 * 128, Wc + (size_t)l * 64 * 128,
            WTpe + (size_t)l * 128 * 192, 128, 64);
        for (int e = 0; e < 2; e++) {
            int li = l * 2 + e;
            transpose_pack<<<(128 * 256 + 255) / 256, 256, 0, s2>>>(
                sWl + (size_t)li * 16384, sWr + (size_t)li * 16384,
                WTsage + (size_t)li * 128 * 256, 128, 128);
        }
    }
    cudaEventRecord(e_wt, s2);

    cudaMemsetAsync(cnt, 0, NT * sizeof(int), s2);
    count2<<<(2 * NE + 255) / 256, 256, 0, s2>>>(edgeAB + NE, edgeBA + NE, cntB, cntA);
    scan2<<<2, 1024, 0, s2>>>(cntA, offA, cntB, offB);
    fill2<<<(2 * NE + 255) / 256, 256, 0, s2>>>(edgeAB, edgeAB + NE, edgeBA, edgeBA + NE,
                                                cntB, cntA, csrAB, csrBA);
    cudaEventRecord(e_csr, s2);

    // ---- default stream: critical path ----
    cudaMemcpyAsync(agg, PE, (size_t)NT * 8 * sizeof(float), cudaMemcpyDeviceToDevice);
    agg_scatter<<<(EHN + 255) / 256, 256>>>(PE, hedge, hedge + EHN, agg, EHN);
    hid_kernel2<<<(NT + 3) / 4, 256>>>(agg, pW1, pb1, hid16, NT);

    cudaStreamWaitEvent(0, e_wt, 0);

    const __half* srcA = x16;
    const __half* srcB = x16 + (size_t)N_A * CC;
    const int blocksA = (N_A + 127) / 128;
    dim3 gGrid(2 * blocksA);
    bool joined_csr = false;

    for (int l = 0; l < 2; l++) {
        const __half* hl = hid16 + (size_t)l * NT * 64;

        gemm_mma<false><<<gGrid, 256, gsm>>>(
            srcA, srcB, 128,
            hl, hl + (size_t)N_A * 64, 64,
            WTpe + (size_t)l * 128 * 192, WTpe + (size_t)l * 128 * 192, 192,
            bc + l * 128, bc + l * 128,
            nullptr, nullptr, nullptr, nullptr,
            nullptr, nullptr, lin16, N_A, N_B, blocksA);

        if (!joined_csr) { cudaStreamWaitEvent(0, e_csr, 0); joined_csr = true; }

        // two rows per warp -> NT/2 warps
        mean_gather4<<<(NT / 2 * 32 + 255) / 256, 256>>>(lin16, csrBA, offA,
                                                         csrAB, offB, m16);

        float* outA = (l == 1) ? out                    : nullptr;
        float* outB = (l == 1) ? out + (size_t)N_A * CC : nullptr;
        __half* o16 = (l == 0) ? cur16 : nullptr;

        gemm_mma<true><<<gGrid, 256, gsm>>>(
            m16, m16 + (size_t)N_A * CC, 128,
            lin16, lin16 + (size_t)N_A * CC, 128,
            WTsage + (size_t)(l * 2 + 1) * 128 * 256,
            WTsage + (size_t)(l * 2 + 0) * 128 * 256, 256,
            sbl + (l * 2 + 1) * 128, sbl + (l * 2 + 0) * 128,
            lng + (l * 2 + 0) * 128, lnb + (l * 2 + 0) * 128,
            lng + (l * 2 + 1) * 128, lnb + (l * 2 + 1) * 128,
            outA, outB, o16, N_A, N_B, blocksA);

        srcA = cur16;
        srcB = cur16 + (size_t)N_A * CC;
    }
}

// round 17
// speedup vs baseline: 1.0445x; 1.0070x over previous
#include <cuda_runtime.h>
#include <cuda_bf16.h>
#include <cuda_fp16.h>
#include <math.h>
#include <stdint.h>

#define N_A 50000
#define N_B 50000
#define NT  100000
#define NE  800000
#define EHN 1600000
#define CC  128

// ---------------- device scratch (static, no allocation) ----------------
__device__ float  g_agg [NT * 8];
__device__ __half g_x16 [NT * CC];
__device__ __half g_hid16[2 * NT * 64];
__device__ __half g_lin16[NT * CC];
__device__ __half g_m16 [NT * CC];
__device__ __half g_cur16[NT * CC];
__device__ int    g_cnt [NT];
__device__ int    g_offA[N_A + 1];
__device__ int    g_offB[N_B + 1];
__device__ int    g_csrAB[NE];
__device__ int    g_csrBA[NE];
__device__ float  g_Wc  [2 * 64 * 128];
__device__ float  g_bc  [2 * 128];
__device__ __half g_WTpe  [2 * 128 * 192];
__device__ __half g_WTsage[4 * 128 * 256];

// ---------------- helpers ----------------
__device__ __forceinline__ uint32_t smem_u32(const void* p) {
    uint32_t a;
    asm("{ .reg .u64 t; cvta.to.shared.u64 t, %1; cvt.u32.u64 %0, t; }" : "=r"(a) : "l"(p));
    return a;
}

__device__ __forceinline__ uint32_t pack_h2(float2 f) {
    __half2 h = __float22half2_rn(f);
    return *(uint32_t*)&h;
}

__device__ __forceinline__ void mma_f16(float c[4], const uint32_t a[4],
                                        uint32_t b0, uint32_t b1) {
    asm volatile(
        "mma.sync.aligned.m16n8k16.row.col.f32.f16.f16.f32 "
        "{%0,%1,%2,%3}, {%4,%5,%6,%7}, {%8,%9}, {%0,%1,%2,%3};"
        : "+f"(c[0]), "+f"(c[1]), "+f"(c[2]), "+f"(c[3])
        : "r"(a[0]), "r"(a[1]), "r"(a[2]), "r"(a[3]), "r"(b0), "r"(b1));
}

__device__ __forceinline__ void cpasync16(uint32_t daddr, const void* g, bool pred) {
    int sz = pred ? 16 : 0;
    asm volatile("cp.async.cg.shared.global [%0], [%1], 16, %2;"
                 :: "r"(daddr), "l"(g), "r"(sz) : "memory");
}
#define CP_COMMIT() asm volatile("cp.async.commit_group;" ::: "memory")

__device__ __forceinline__ void red4(float* addr, float4 v) {
    asm volatile("red.global.add.v4.f32 [%0], {%1,%2,%3,%4};"
                 :: "l"(addr), "f"(v.x), "f"(v.y), "f"(v.z), "f"(v.w) : "memory");
}

// ---------------- graph preprocessing (merged two-direction kernels) ----------------
__global__ void count2(const int* __restrict__ dstAB, const int* __restrict__ dstBA,
                       int* __restrict__ cntB, int* __restrict__ cntA) {
    int e = blockIdx.x * blockDim.x + threadIdx.x;
    if (e < NE)            atomicAdd(&cntB[dstAB[e]], 1);
    else if (e < 2 * NE)   atomicAdd(&cntA[dstBA[e - NE]], 1);
}

__global__ void scan2(int* __restrict__ cntA, int* __restrict__ offA,
                      int* __restrict__ cntB, int* __restrict__ offB) {
    __shared__ int part[1024];
    int* cnt = blockIdx.x ? cntB : cntA;
    int* off = blockIdx.x ? offB : offA;
    const int N = N_A;
    int tid = threadIdx.x;
    int chunk = (N + 1023) >> 10;
    int start = tid * chunk;
    int end = min(start + chunk, N);
    int s = 0;
    for (int i = start; i < end; i++) s += cnt[i];
    part[tid] = s;
    __syncthreads();
    for (int o = 1; o < 1024; o <<= 1) {
        int t = (tid >= o) ? part[tid - o] : 0;
        __syncthreads();
        part[tid] += t;
        __syncthreads();
    }
    int pre = part[tid] - s;
    for (int i = start; i < end; i++) {
        int c = cnt[i];
        off[i] = pre;
        cnt[i] = pre;
        pre += c;
    }
    if (tid == 1023) off[N] = part[1023];
}

__global__ void fill2(const int* __restrict__ srcAB, const int* __restrict__ dstAB,
                      const int* __restrict__ srcBA, const int* __restrict__ dstBA,
                      int* __restrict__ posB, int* __restrict__ posA,
                      int* __restrict__ csrAB, int* __restrict__ csrBA) {
    int e = blockIdx.x * blockDim.x + threadIdx.x;
    if (e < NE) {
        int p = atomicAdd(&posB[dstAB[e]], 1);
        csrAB[p] = srcAB[e];
    } else if (e < 2 * NE) {
        int i = e - NE;
        int p = atomicAdd(&posA[dstBA[i]], 1);
        csrBA[p] = srcBA[i];
    }
}

__global__ void agg_scatter(const float* __restrict__ PE, const int* __restrict__ hsrc,
                            const int* __restrict__ hdst, float* __restrict__ agg, int E) {
    int e = blockIdx.x * blockDim.x + threadIdx.x;
    if (e >= E) return;
    int s = hsrc[e], d = hdst[e];
    float4 v0 = *(const float4*)(PE + (size_t)s * 8);
    float4 v1 = *(const float4*)(PE + (size_t)s * 8 + 4);
    red4(agg + (size_t)d * 8,     v0);
    red4(agg + (size_t)d * 8 + 4, v1);
}

__global__ void fold_w(const float* __restrict__ W2, const float* __restrict__ peWpe,
                       float* __restrict__ Wc) {
    int idx = blockIdx.x * blockDim.x + threadIdx.x;
    if (idx >= 64 * 128) return;
    int i = idx >> 7, j = idx & 127;
    float s = 0.0f;
    #pragma unroll 8
    for (int p = 0; p < 64; p++) s += W2[i * 64 + p] * peWpe[p * 128 + j];
    Wc[idx] = s;
}

__global__ void fold_b(const float* __restrict__ b2, const float* __restrict__ peWpe,
                       const float* __restrict__ peb, float* __restrict__ bc) {
    int j = threadIdx.x;
    float s = peb[j];
    #pragma unroll 8
    for (int p = 0; p < 64; p++) s += b2[p] * peWpe[p * 128 + j];
    bc[j] = s;
}

__global__ void transpose_pack(const float* __restrict__ Wl, const float* __restrict__ Wr,
                               __half* __restrict__ WT, int Kl, int Kr) {
    int K = Kl + Kr;
    int idx = blockIdx.x * blockDim.x + threadIdx.x;
    if (idx >= 128 * K) return;
    int n = idx / K, k = idx % K;
    float w = (k < Kl) ? Wl[(size_t)k * 128 + n] : Wr[(size_t)(k - Kl) * 128 + n];
    WT[idx] = __float2half_rn(w);
}

__global__ void conv_x16(const float* __restrict__ xA, const float* __restrict__ xB,
                         __half* __restrict__ x16) {
    int idx = blockIdx.x * blockDim.x + threadIdx.x;
    if (idx >= NT * CC / 4) return;
    size_t e = (size_t)idx * 4;
    size_t row = e >> 7;
    const float* src = (row < N_A) ? (xA + e) : (xB + (e - (size_t)N_A * CC));
    float4 v = *(const float4*)src;
    uint2 o;
    o.x = pack_h2(make_float2(v.x, v.y));
    o.y = pack_h2(make_float2(v.z, v.w));
    *(uint2*)(x16 + e) = o;
}

__global__ void hid_kernel2(const float* __restrict__ agg,
                            const float* __restrict__ W1, const float* __restrict__ b1,
                            __half* __restrict__ hid, int NTn) {
    __shared__ float sW1[2][512];
    __shared__ float sb1[2][64];
    int tid = threadIdx.x;
    for (int i = tid; i < 512; i += 256) { sW1[0][i] = W1[i]; sW1[1][i] = W1[512 + i]; }
    if (tid < 64) { sb1[0][tid] = b1[tid]; sb1[1][tid] = b1[64 + tid]; }
    __syncthreads();
    int r = tid >> 6, j = tid & 63;
    int row = blockIdx.x * 4 + r;
    if (row < NTn) {
        float a[8];
        #pragma unroll
        for (int k = 0; k < 8; k++) a[k] = agg[(size_t)row * 8 + k];
        #pragma unroll
        for (int l = 0; l < 2; l++) {
            float h = sb1[l][j];
            #pragma unroll
            for (int k = 0; k < 8; k++) h += a[k] * sW1[l][k * 64 + j];
            hid[(size_t)l * NT * 64 + (size_t)row * 64 + j] = __float2half_rn(fmaxf(h, 0.0f));
        }
    }
}

// ---------------- per-side CSR mean gather: two rows/warp, 16B loads/lane -------------
// dst rows [0, N_A) of the given side; sources at srcBase; output at dstBase.
__global__ void mean_gather_side(const __half* __restrict__ lin16,
                                 const int* __restrict__ csr, const int* __restrict__ off,
                                 int srcBase, int dstBase, __half* __restrict__ m16)
{
    int gw = (blockIdx.x * blockDim.x + threadIdx.x) >> 5;
    int lane = threadIdx.x & 31;
    int rr = gw * 2 + (lane >> 4);
    if (rr >= N_A) return;                 // N_A == N_B
    int s0 = off[rr], s1 = off[rr + 1];
    int colh = (lane & 15) * 8;

    float a0=0.f,a1=0.f,a2=0.f,a3=0.f,a4=0.f,a5=0.f,a6=0.f,a7=0.f;
    int i = s0;
    for (; i + 2 <= s1; i += 2) {
        int i0 = __ldg(csr + i), i1 = __ldg(csr + i + 1);
        uint4 p0 = *(const uint4*)(lin16 + (size_t)(srcBase + i0) * CC + colh);
        uint4 p1 = *(const uint4*)(lin16 + (size_t)(srcBase + i1) * CC + colh);
        {
            float2 f0 = __half22float2(*(__half2*)&p0.x);
            float2 f1 = __half22float2(*(__half2*)&p0.y);
            float2 f2 = __half22float2(*(__half2*)&p0.z);
            float2 f3 = __half22float2(*(__half2*)&p0.w);
            a0 += f0.x; a1 += f0.y; a2 += f1.x; a3 += f1.y;
            a4 += f2.x; a5 += f2.y; a6 += f3.x; a7 += f3.y;
        }
        {
            float2 f0 = __half22float2(*(__half2*)&p1.x);
            float2 f1 = __half22float2(*(__half2*)&p1.y);
            float2 f2 = __half22float2(*(__half2*)&p1.z);
            float2 f3 = __half22float2(*(__half2*)&p1.w);
            a0 += f0.x; a1 += f0.y; a2 += f1.x; a3 += f1.y;
            a4 += f2.x; a5 += f2.y; a6 += f3.x; a7 += f3.y;
        }
    }
    if (i < s1) {
        int i0 = __ldg(csr + i);
        uint4 p0 = *(const uint4*)(lin16 + (size_t)(srcBase + i0) * CC + colh);
        float2 f0 = __half22float2(*(__half2*)&p0.x);
        float2 f1 = __half22float2(*(__half2*)&p0.y);
        float2 f2 = __half22float2(*(__half2*)&p0.z);
        float2 f3 = __half22float2(*(__half2*)&p0.w);
        a0 += f0.x; a1 += f0.y; a2 += f1.x; a3 += f1.y;
        a4 += f2.x; a5 += f2.y; a6 += f3.x; a7 += f3.y;
    }
    float sc = 1.0f / (float)max(s1 - s0, 1);
    uint4 o;
    o.x = pack_h2(make_float2(a0 * sc, a1 * sc));
    o.y = pack_h2(make_float2(a2 * sc, a3 * sc));
    o.z = pack_h2(make_float2(a4 * sc, a5 * sc));
    o.w = pack_h2(make_float2(a6 * sc, a7 * sc));
    *(uint4*)(m16 + (size_t)(dstBase + rr) * CC + colh) = o;
}

// ---------------- fp16 mma.sync GEMM (2-stage cp.async, side-selectable launch) --------
#define T_TILE_H 3072                 // 128 * 24 halfs per tile buffer
#define GEMM_SMEM_F (640 + 4 * (T_TILE_H / 2))

__device__ __forceinline__ void load_tile(
    const __half* __restrict__ X0, int K0, const __half* __restrict__ X1, int K1,
    const __half* __restrict__ WT, int K, int m0, int M, int t,
    uint32_t asAddr, uint32_t bsAddr, int tid)
{
    int kb = t * 16;
    {
        int row = tid >> 1, c = tid & 1;
        int kk = kb + c * 8;
        bool pred = (m0 + row) < M;
        const __half* src = (kk < K0)
            ? X0 + (size_t)(m0 + row) * K0 + kk
            : X1 + (size_t)(m0 + row) * K1 + (kk - K0);
        cpasync16(asAddr + (uint32_t)(row * 24 + c * 8) * 2, src, pred);
    }
    {
        int n = tid >> 1, c = tid & 1;
        cpasync16(bsAddr + (uint32_t)(n * 24 + c * 8) * 2,
                  WT + (size_t)n * K + kb + c * 8, true);
    }
    CP_COMMIT();
}

template<bool DO_LN>
__global__ void __launch_bounds__(256, 2)
gemm_mma(const __half* X0a, const __half* X0b, int K0,
         const __half* X1a, const __half* X1b, int K1,
         const __half* WTa, const __half* WTb, int K,
         const float* biasA, const float* biasB,
         const float* gamA, const float* betA,
         const float* gamB, const float* betB,
         float* outA, float* outB, __half* out16,
         int Ma, int Mb, int blocksA)
{
    extern __shared__ float sm[];
    float* s_bias  = sm;
    float* s_gamma = sm + 128;
    float* s_beta  = sm + 256;
    float* s_sum   = sm + 384;
    float* s_ss    = sm + 512;
    __half* As     = (__half*)(sm + 640);
    __half* Bs     = As + 2 * T_TILE_H;

    bool isB = (int)blockIdx.x >= blocksA;
    const __half* X0  = isB ? X0b  : X0a;
    const __half* X1  = isB ? X1b  : X1a;
    const __half* WT  = isB ? WTb  : WTa;
    const float* bias = isB ? biasB : biasA;
    const float* gamma = isB ? gamB : gamA;
    const float* beta  = isB ? betB : betA;
    float* out = isB ? outB : outA;
    int M  = isB ? Mb : Ma;
    int mrow0 = (isB ? ((int)blockIdx.x - blocksA) : (int)blockIdx.x) * 128;
    size_t row16base = isB ? (size_t)N_A : 0;

    int tid  = threadIdx.x;
    int lane = tid & 31;
    int warp = tid >> 5;
    int wm = warp & 3;
    int wn = warp >> 2;

    if (tid < 128) {
        s_bias[tid] = bias[tid];
        if (DO_LN) {
            s_gamma[tid] = gamma[tid];
            s_beta[tid]  = beta[tid];
            s_sum[tid] = 0.0f;
            s_ss[tid]  = 0.0f;
        }
    }

    uint32_t asAddr = smem_u32(As);
    uint32_t bsAddr = smem_u32(Bs);

    float c[2][8][4];
    #pragma unroll
    for (int mt = 0; mt < 2; mt++)
        #pragma unroll
        for (int nt = 0; nt < 8; nt++)
            #pragma unroll
            for (int j = 0; j < 4; j++) c[mt][nt][j] = 0.0f;

    const int T = K / 16;
    load_tile(X0, K0, X1, K1, WT, K, mrow0, M, 0, asAddr, bsAddr, tid);
    load_tile(X0, K0, X1, K1, WT, K, mrow0, M, 1,
              asAddr + T_TILE_H * 2, bsAddr + T_TILE_H * 2, tid);

    int kq = 2 * (lane & 3);

    for (int t = 0; t < T; t++) {
        if (t + 1 < T) asm volatile("cp.async.wait_group 1;" ::: "memory");
        else           asm volatile("cp.async.wait_group 0;" ::: "memory");
        __syncthreads();

        const __half* Ab = As + (t & 1) * T_TILE_H;
        const __half* Bb = Bs + (t & 1) * T_TILE_H;

        uint32_t a[2][4];
        #pragma unroll
        for (int mt = 0; mt < 2; mt++) {
            int rb = wm * 32 + mt * 16 + (lane >> 2);
            a[mt][0] = *(const uint32_t*)(Ab + rb * 24 + kq);
            a[mt][1] = *(const uint32_t*)(Ab + (rb + 8) * 24 + kq);
            a[mt][2] = *(const uint32_t*)(Ab + rb * 24 + kq + 8);
            a[mt][3] = *(const uint32_t*)(Ab + (rb + 8) * 24 + kq + 8);
        }
        #pragma unroll
        for (int nt = 0; nt < 8; nt++) {
            int nb = wn * 64 + nt * 8 + (lane >> 2);
            uint32_t b0 = *(const uint32_t*)(Bb + nb * 24 + kq);
            uint32_t b1 = *(const uint32_t*)(Bb + nb * 24 + kq + 8);
            mma_f16(c[0][nt], a[0], b0, b1);
            mma_f16(c[1][nt], a[1], b0, b1);
        }
        __syncthreads();
        if (t + 2 < T)
            load_tile(X0, K0, X1, K1, WT, K, mrow0, M, t + 2,
                      asAddr + (uint32_t)(t & 1) * T_TILE_H * 2,
                      bsAddr + (uint32_t)(t & 1) * T_TILE_H * 2, tid);
    }

    // ---- add bias ----
    #pragma unroll
    for (int nt = 0; nt < 8; nt++) {
        int col = wn * 64 + nt * 8 + 2 * (lane & 3);
        float bx = s_bias[col], by = s_bias[col + 1];
        #pragma unroll
        for (int mt = 0; mt < 2; mt++) {
            c[mt][nt][0] += bx; c[mt][nt][1] += by;
            c[mt][nt][2] += bx; c[mt][nt][3] += by;
        }
    }

    if (!DO_LN) {
        #pragma unroll
        for (int mt = 0; mt < 2; mt++)
            #pragma unroll
            for (int h = 0; h < 2; h++) {
                int rloc = wm * 32 + mt * 16 + (lane >> 2) + h * 8;
                int row = mrow0 + rloc;
                if (row < M) {
                    #pragma unroll
                    for (int nt = 0; nt < 8; nt++) {
                        int col = wn * 64 + nt * 8 + 2 * (lane & 3);
                        uint32_t o16 = pack_h2(make_float2(c[mt][nt][h * 2], c[mt][nt][h * 2 + 1]));
                        *(uint32_t*)(out16 + (row16base + row) * 128 + col) = o16;
                    }
                }
            }
        return;
    }

    // ---- LayerNorm + ReLU ----
    #pragma unroll
    for (int mt = 0; mt < 2; mt++)
        #pragma unroll
        for (int h = 0; h < 2; h++) {
            float s = 0.f, q = 0.f;
            #pragma unroll
            for (int nt = 0; nt < 8; nt++) {
                float v0 = c[mt][nt][h * 2], v1 = c[mt][nt][h * 2 + 1];
                s += v0 + v1;
                q += v0 * v0 + v1 * v1;
            }
            s += __shfl_xor_sync(0xffffffffu, s, 1);
            s += __shfl_xor_sync(0xffffffffu, s, 2);
            q += __shfl_xor_sync(0xffffffffu, q, 1);
            q += __shfl_xor_sync(0xffffffffu, q, 2);
            if ((lane & 3) == 0) {
                int rl = wm * 32 + mt * 16 + (lane >> 2) + h * 8;
                atomicAdd(&s_sum[rl], s);
                atomicAdd(&s_ss[rl], q);
            }
        }
    __syncthreads();
    #pragma unroll
    for (int mt = 0; mt < 2; mt++)
        #pragma unroll
        for (int h = 0; h < 2; h++) {
            int rl = wm * 32 + mt * 16 + (lane >> 2) + h * 8;
            int row = mrow0 + rl;
            float mu   = s_sum[rl] * (1.0f / 128.0f);
            float var  = s_ss[rl] * (1.0f / 128.0f) - mu * mu;
            float rstd = rsqrtf(var + 1e-5f);
            if (row < M) {
                #pragma unroll
                for (int nt = 0; nt < 8; nt++) {
                    int col = wn * 64 + nt * 8 + 2 * (lane & 3);
                    float2 o;
                    o.x = fmaxf((c[mt][nt][h * 2]     - mu) * rstd * s_gamma[col]     + s_beta[col],     0.f);
                    o.y = fmaxf((c[mt][nt][h * 2 + 1] - mu) * rstd * s_gamma[col + 1] + s_beta[col + 1], 0.f);
                    if (out)
                        *(float2*)(out + (size_t)row * 128 + col) = o;
                    if (out16)
                        *(uint32_t*)(out16 + (row16base + row) * 128 + col) = pack_h2(o);
                }
            }
        }
}

// ---------------- launch ----------------
extern "C" void kernel_launch(void* const* d_in, const int* in_sizes, int n_in,
                              void* d_out, int out_size)
{
    const float* xA     = (const float*)d_in[0];
    const float* xB     = (const float*)d_in[1];
    const float* PE     = (const float*)d_in[2];
    const int*   edgeAB = (const int*)  d_in[3];
    const int*   edgeBA = (const int*)  d_in[4];
    const int*   hedge  = (const int*)  d_in[5];
    const float* sWl    = (const float*)d_in[6];
    const float* sbl    = (const float*)d_in[7];
    const float* sWr    = (const float*)d_in[8];
    const float* lng    = (const float*)d_in[9];
    const float* lnb    = (const float*)d_in[10];
    const float* pW1    = (const float*)d_in[11];
    const float* pb1    = (const float*)d_in[12];
    const float* pW2    = (const float*)d_in[13];
    const float* pb2    = (const float*)d_in[14];
    const float* peW    = (const float*)d_in[15];
    const float* peb    = (const float*)d_in[16];
    float* out = (float*)d_out;

    float *agg, *Wc, *bc;
    __half *x16, *hid16, *lin16, *m16, *cur16, *WTpe, *WTsage;
    int *cnt, *offA, *offB, *csrAB, *csrBA;
    cudaGetSymbolAddress((void**)&agg,    g_agg);
    cudaGetSymbolAddress((void**)&x16,    g_x16);
    cudaGetSymbolAddress((void**)&hid16,  g_hid16);
    cudaGetSymbolAddress((void**)&lin16,  g_lin16);
    cudaGetSymbolAddress((void**)&m16,    g_m16);
    cudaGetSymbolAddress((void**)&cur16,  g_cur16);
    cudaGetSymbolAddress((void**)&cnt,    g_cnt);
    cudaGetSymbolAddress((void**)&offA,   g_offA);
    cudaGetSymbolAddress((void**)&offB,   g_offB);
    cudaGetSymbolAddress((void**)&csrAB,  g_csrAB);
    cudaGetSymbolAddress((void**)&csrBA,  g_csrBA);
    cudaGetSymbolAddress((void**)&Wc,     g_Wc);
    cudaGetSymbolAddress((void**)&bc,     g_bc);
    cudaGetSymbolAddress((void**)&WTpe,   g_WTpe);
    cudaGetSymbolAddress((void**)&WTsage, g_WTsage);
    int* cntA = cnt;
    int* cntB = cnt + N_A;

    size_t gsm = GEMM_SMEM_F * sizeof(float);
    cudaFuncSetAttribute(gemm_mma<false>, cudaFuncAttributeMaxDynamicSharedMemorySize, (int)gsm);
    cudaFuncSetAttribute(gemm_mma<true>,  cudaFuncAttributeMaxDynamicSharedMemorySize, (int)gsm);

    cudaStream_t s2;
    cudaStreamCreateWithFlags(&s2, cudaStreamNonBlocking);
    cudaEvent_t e0, e_wt, eB[2], eA[2], gA[2], gB[2];
    cudaEventCreateWithFlags(&e0,   cudaEventDisableTiming);
    cudaEventCreateWithFlags(&e_wt, cudaEventDisableTiming);
    for (int l = 0; l < 2; l++) {
        cudaEventCreateWithFlags(&eB[l], cudaEventDisableTiming);
        cudaEventCreateWithFlags(&eA[l], cudaEventDisableTiming);
        cudaEventCreateWithFlags(&gA[l], cudaEventDisableTiming);
        cudaEventCreateWithFlags(&gB[l], cudaEventDisableTiming);
    }

    cudaEventRecord(e0, 0);
    cudaStreamWaitEvent(s2, e0, 0);

    // ---- s2: x16 conversion + weight folds/transposes, then compact CSR chain ----
    conv_x16<<<(NT * CC / 4 + 255) / 256, 256, 0, s2>>>(xA, xB, x16);
    for (int l = 0; l < 2; l++) {
        const float* peWpe = peW + (size_t)l * 192 * 128 + 128 * 128;
        fold_w<<<32, 256, 0, s2>>>(pW2 + l * 4096, peWpe, Wc + (size_t)l * 64 * 128);
        fold_b<<<1, 128, 0, s2>>>(pb2 + l * 64, peWpe, peb + l * 128, bc + l * 128);
        transpose_pack<<<(128 * 192 + 255) / 256, 256, 0, s2>>>(
            peW + (size_t)l * 192 * 128, Wc + (size_t)l * 64 * 128,
            WTpe + (size_t)l * 128 * 192, 128, 64);
        for (int e = 0; e < 2; e++) {
            int li = l * 2 + e;
            transpose_pack<<<(128 * 256 + 255) / 256, 256, 0, s2>>>(
                sWl + (size_t)li * 16384, sWr + (size_t)li * 16384,
                WTsage + (size_t)li * 128 * 256, 128, 128);
        }
    }
    cudaEventRecord(e_wt, s2);

    cudaMemsetAsync(cnt, 0, NT * sizeof(int), s2);
    count2<<<(2 * NE + 255) / 256, 256, 0, s2>>>(edgeAB + NE, edgeBA + NE, cntB, cntA);
    scan2<<<2, 1024, 0, s2>>>(cntA, offA, cntB, offB);
    fill2<<<(2 * NE + 255) / 256, 256, 0, s2>>>(edgeAB, edgeAB + NE, edgeBA, edgeBA + NE,
                                                cntB, cntA, csrAB, csrBA);
    // gathers run on s2 after fill2 — naturally ordered, no csr event needed

    // ---- default stream: critical path ----
    cudaMemcpyAsync(agg, PE, (size_t)NT * 8 * sizeof(float), cudaMemcpyDeviceToDevice);
    agg_scatter<<<(EHN + 255) / 256, 256>>>(PE, hedge, hedge + EHN, agg, EHN);
    hid_kernel2<<<(NT + 3) / 4, 256>>>(agg, pW1, pb1, hid16, NT);

    cudaStreamWaitEvent(0, e_wt, 0);

    const __half* srcA = x16;
    const __half* srcB = x16 + (size_t)N_A * CC;
    const int halfBlocks = (N_A + 127) / 128;   // 391
    const int gatherBlocks = (N_A / 2 * 32 + 255) / 256;
    __half* lin16B = lin16 + (size_t)N_A * CC;
    __half* m16B   = m16   + (size_t)N_A * CC;

    for (int l = 0; l < 2; l++) {
        const __half* hl = hid16 + (size_t)l * NT * 64;
        const __half* hlB = hl + (size_t)N_A * 64;
        const __half* WTp = WTpe + (size_t)l * 128 * 192;

        // --- pe-linear, B half first (enables gatherA) ---
        gemm_mma<false><<<halfBlocks, 256, gsm>>>(
            srcA, srcB, 128, hl, hlB, 64,
            WTp, WTp, 192, bc + l * 128, bc + l * 128,
            nullptr, nullptr, nullptr, nullptr,
            nullptr, nullptr, lin16, N_A, N_B, /*blocksA=*/0);      // all-B
        cudaEventRecord(eB[l], 0);

        // --- pe-linear, A half ---
        gemm_mma<false><<<halfBlocks, 256, gsm>>>(
            srcA, srcB, 128, hl, hlB, 64,
            WTp, WTp, 192, bc + l * 128, bc + l * 128,
            nullptr, nullptr, nullptr, nullptr,
            nullptr, nullptr, lin16, N_A, N_B, /*blocksA=*/halfBlocks); // all-A
        cudaEventRecord(eA[l], 0);

        // --- s2: gatherA (A-dst from B-src) overlaps peA ---
        cudaStreamWaitEvent(s2, eB[l], 0);
        mean_gather_side<<<gatherBlocks, 256, 0, s2>>>(lin16, csrBA, offA,
                                                       /*srcBase=*/N_A, /*dstBase=*/0, m16);
        cudaEventRecord(gA[l], s2);

        // --- s2: gatherB (B-dst from A-src) overlaps sageA ---
        cudaStreamWaitEvent(s2, eA[l], 0);
        mean_gather_side<<<gatherBlocks, 256, 0, s2>>>(lin16, csrAB, offB,
                                                       /*srcBase=*/0, /*dstBase=*/N_A, m16);
        cudaEventRecord(gB[l], s2);

        float* outA = (l == 1) ? out                    : nullptr;
        float* outB = (l == 1) ? out + (size_t)N_A * CC : nullptr;
        __half* o16 = (l == 0) ? cur16 : nullptr;

        // --- SAGE A half (needs m16 A + lin16 A) ---
        cudaStreamWaitEvent(0, gA[l], 0);
        gemm_mma<true><<<halfBlocks, 256, gsm>>>(
            m16, m16B, 128, lin16, lin16B, 128,
            WTsage + (size_t)(l * 2 + 1) * 128 * 256,
            WTsage + (size_t)(l * 2 + 0) * 128 * 256, 256,
            sbl + (l * 2 + 1) * 128, sbl + (l * 2 + 0) * 128,
            lng + (l * 2 + 0) * 128, lnb + (l * 2 + 0) * 128,
            lng + (l * 2 + 1) * 128, lnb + (l * 2 + 1) * 128,
            outA, outB, o16, N_A, N_B, /*blocksA=*/halfBlocks);     // all-A

        // --- SAGE B half ---
        cudaStreamWaitEvent(0, gB[l], 0);
        gemm_mma<true><<<halfBlocks, 256, gsm>>>(
            m16, m16B, 128, lin16, lin16B, 128,
            WTsage + (size_t)(l * 2 + 1) * 128 * 256,
            WTsage + (size_t)(l * 2 + 0) * 128 * 256, 256,
            sbl + (l * 2 + 1) * 128, sbl + (l * 2 + 0) * 128,
            lng + (l * 2 + 0) * 128, lnb + (l * 2 + 0) * 128,
            lng + (l * 2 + 1) * 128, lnb + (l * 2 + 1) * 128,
            outA, outB, o16, N_A, N_B, /*blocksA=*/0);              // all-B

        srcA = cur16;
        srcB = cur16 + (size_t)N_A * CC;
    }
}